// round 13
// baseline (speedup 1.0000x reference)
#include <cuda_runtime.h>

// ---------------- problem constants ----------------
#define NN    16384
#define EE    65536
#define HH    32
#define BBAT  32
#define NPERB 512
#define NLAY  4
#define APITCH 324      // A smem pitch; row strides map to disjoint bank quads
#define GSMEMF (32 * APITCH)          // 10368 floats = 41.5KB (partials reuse this region)
#define GSMEMB (GSMEMF * 4)

// ---------------- scratch (static device globals; zero at load) ----------------
__device__ __align__(128) float g_xbuf[2][NN * HH];
__device__ __align__(128) float g_agg2[NN * 288];      // edge-agg output (scaled)
__device__ __align__(128) float g_B[NLAY * 320 * HH];  // chunk-major: [l][kc][col][j] j=k%4
__device__ int   g_deg[NN];
__device__ float g_invdeg[NN];
__device__ int   g_rowstart[NN + 1];
__device__ int   g_cursor[NN];
__device__ int   g_payload[EE];                        // (src<<4)|attr, grouped by dst
__device__ int   g_bsum[64];
__device__ int   g_barrier;
__device__ int   g_done;

// ---------------- f32x2 helpers ----------------
__device__ __forceinline__ unsigned long long fma2(unsigned long long a,
                                                   unsigned long long b,
                                                   unsigned long long c) {
    unsigned long long d;
    asm("fma.rn.f32x2 %0, %1, %2, %3;" : "=l"(d) : "l"(a), "l"(b), "l"(c));
    return d;
}
__device__ __forceinline__ float fold2(unsigned long long v) {
    unsigned int lo, hi;
    asm("mov.b64 {%0, %1}, %2;" : "=r"(lo), "=r"(hi) : "l"(v));
    return __uint_as_float(lo) + __uint_as_float(hi);
}

// ================= K1: fused setup ==========================================
__global__ __launch_bounds__(256) void k_setup(const int* __restrict__ xn,
                                               const float* __restrict__ nemb,
                                               const float* __restrict__ lin_w,
                                               const float* __restrict__ lin_b,
                                               const float* __restrict__ root_w,
                                               const int* __restrict__ edge_index) {
    int b = blockIdx.x, t = threadIdx.x;
    if (b < 512) {
        int i = b * 256 + t;
        int node = i >> 3, q = i & 7;
        float4 v = __ldg((const float4*)(nemb + xn[node] * HH + q * 4));
        ((float4*)g_xbuf[0])[i] = v;
    } else if (b < 672) {
        int i = (b - 512) * 256 + t;         // < 40960
        int l = i / 10240;
        int rem = i - l * 10240;
        int kc = rem >> 7;                   // k-chunk 0..79
        int r2 = rem & 127;
        int c = r2 >> 2, j = r2 & 3;         // col, k-within-chunk
        int k = kc * 4 + j;
        float v;
        if (k < 256)      v = lin_w[l * 8192 + (k >> 5) * 1024 + (k & 31) * 32 + c];
        else if (k < 288) v = lin_b[l * 1024 + (k - 256) * 32 + c];
        else              v = root_w[l * 1024 + (k - 288) * 32 + c];
        g_B[i] = v;
    } else {
        int i = (b - 672) * 256 + t;
        int4 d4 = __ldg((const int4*)(edge_index + EE) + i);
        atomicAdd(&g_deg[d4.x], 1);
        atomicAdd(&g_deg[d4.y], 1);
        atomicAdd(&g_deg[d4.z], 1);
        atomicAdd(&g_deg[d4.w], 1);
    }
}

// ================= K2: fused scan + scatter (64 blocks resident) ==============
__global__ __launch_bounds__(256) void k_scan_scatter(const int* __restrict__ edge_index,
                                                      const int* __restrict__ edge_attr) {
    __shared__ int sw[8];
    __shared__ int sb[64];
    int tid = threadIdx.x, w = tid >> 5, lane = tid & 31, b = blockIdx.x;
    int n = b * 256 + tid;
    int d = g_deg[n];

    int incl = d;
#pragma unroll
    for (int off = 1; off < 32; off <<= 1) {
        int v = __shfl_up_sync(0xFFFFFFFFu, incl, off);
        if (lane >= off) incl += v;
    }
    if (lane == 31) sw[w] = incl;
    __syncthreads();
    int woff = 0, btot = 0;
#pragma unroll
    for (int j = 0; j < 8; j++) { if (j < w) woff += sw[j]; btot += sw[j]; }

    if (tid == 0) {
        g_bsum[b] = btot;
        __threadfence();
        atomicAdd(&g_barrier, 1);
        while (atomicAdd(&g_barrier, 0) < 64) { }
        __threadfence();
    }
    __syncthreads();

    if (tid < 64) sb[tid] = g_bsum[tid];
    __syncthreads();
    int base = 0;
    for (int j = 0; j < b; j++) base += sb[j];

    int excl = base + woff + incl - d;
    g_rowstart[n] = excl;
    g_cursor[n]   = excl;
    g_invdeg[n]   = 1.0f / (float)(d > 0 ? d : 1);
    if (n == NN - 1) g_rowstart[NN] = excl + d;

    __threadfence();
    __syncthreads();
    if (tid == 0) {
        atomicAdd(&g_barrier, 1);
        while (atomicAdd(&g_barrier, 0) < 128) { }
        __threadfence();
    }
    __syncthreads();

#pragma unroll
    for (int q = 0; q < 4; q++) {
        int e = b * 1024 + q * 256 + tid;
        int dd = edge_index[EE + e];
        int pos = atomicAdd(&g_cursor[dd], 1);
        g_payload[pos] = (edge_index[e] << 4) | edge_attr[e];
    }
    __syncthreads();
    if (tid == 0) {
        int c = atomicAdd(&g_done, 1);
        if (c == 63) { g_done = 0; g_barrier = 0; __threadfence(); }
    }
}

// ================= K3: edge aggregation (warp per node, pipelined) ============
// payload prefetch depth 2, x prefetch depth 1: the x-gather for edge t+1 is
// issued before the FMAs of edge t, so successive L2 gathers overlap.
__global__ __launch_bounds__(256) void k_edge(const float* __restrict__ eemb,
                                              int inbuf, int l) {
    __shared__ float cs[128];
    int tid = threadIdx.x;
    if (tid < 128) cs[tid] = fmaxf(eemb[l * 128 + tid], 0.0f);
    __syncthreads();

    int w = tid >> 5, lane = tid & 31;
    int n = blockIdx.x * 8 + w;
    const float* __restrict__ xin = g_xbuf[inbuf];

    int rs = 0;
    if (lane < 2) rs = g_rowstart[n + lane];
    int b0 = __shfl_sync(0xFFFFFFFFu, rs, 0);
    int b1 = __shfl_sync(0xFFFFFFFFu, rs, 1);
    int cnt = b1 - b0;

    float acc[9];
#pragma unroll
    for (int j = 0; j < 9; j++) acc[j] = 0.0f;

    int p0 = (0 < cnt) ? g_payload[b0] : 0;
    int p1 = (1 < cnt) ? g_payload[b0 + 1] : 0;
    float xv = (0 < cnt) ? __ldg(&xin[(p0 >> 4) * HH + lane]) : 0.0f;

    for (int t = 0; t < cnt; t++) {
        int p2 = (t + 2 < cnt) ? g_payload[b0 + t + 2] : 0;
        float xvn = (t + 1 < cnt) ? __ldg(&xin[(p1 >> 4) * HH + lane]) : 0.0f;
        const float* cc = &cs[(p0 & 15) * 8];
#pragma unroll
        for (int j = 0; j < 8; j++) acc[j] = fmaf(cc[j], xv, acc[j]);
        acc[8] += xv;
        p0 = p1; p1 = p2; xv = xvn;
    }
    float inv = g_invdeg[n];
    float* out = g_agg2 + n * 288 + lane;
#pragma unroll
    for (int j = 0; j < 9; j++) out[j * 32] = acc[j] * inv;
}

// ================= K4: GEMM  x_new = [agg2 ; x] @ B_l + conv_b ================
// 512 blocks x 256 thr, 32 rows/block. A staged to smem; B read from global
// chunk-major layout with EXPLICIT double buffering: load B(g+1) is issued a
// full compute-block before it is consumed, hiding even L2 latency.
// warp = (ks: k-slice of 160) x (rq: row octet). lane: rg=lane>>3 -> row pair
// {rq*8+rg*2, +1}; cg=lane&7 -> cols {cg+8ci}. Thread tile 2x4, acc 16 regs.
__global__ __launch_bounds__(256, 3) void k_gemm(const float* __restrict__ conv_b,
                                                 int inbuf, int l, int do_relu) {
    extern __shared__ float sm[];
    float* As = sm;
    int tid = threadIdx.x;
    int n0 = blockIdx.x * 32;
    const float* __restrict__ xin = g_xbuf[inbuf];

    // stage A cols 0..287 from agg2 (coalesced float4)
#pragma unroll
    for (int i = 0; i < 9; i++) {
        int idx = tid + i * 256;            // < 2304
        int row = idx / 72, kc = idx - row * 72;
        float4 v = __ldg((const float4*)(g_agg2 + (n0 + row) * 288) + kc);
        *(float4*)(As + row * APITCH + kc * 4) = v;
    }
    // stage A cols 288..319 = x rows (root path)
    {
        int row = tid >> 3, q = tid & 7;
        float4 v = __ldg((const float4*)(xin + (n0 + row) * HH) + q);
        *(float4*)(As + row * APITCH + 288 + q * 4) = v;
    }
    __syncthreads();

    int w = tid >> 5, lane = tid & 31;
    int ks = w & 1, rq = w >> 1;          // k-slice of 160 (40 chunks); row octet
    int rg = lane >> 3, cg = lane & 7;
    int row0 = rq * 8 + rg * 2;
    const float4* __restrict__ B4 = (const float4*)(g_B + l * 10240);

    unsigned long long ac[8];             // [r(2)][c(4)]
#pragma unroll
    for (int i = 0; i < 8; i++) ac[i] = 0ull;

    int kc0 = ks * 40;
    const float* Ar0 = As + row0 * APITCH;
    const float* Ar1 = As + (row0 + 1) * APITCH;

    float4 bb0[4], bb1[4];
#pragma unroll
    for (int ci = 0; ci < 4; ci++) bb0[ci] = __ldg(B4 + kc0 * 32 + cg + 8 * ci);

#pragma unroll 1
    for (int g = 0; g < 40; g += 2) {
        int kc = kc0 + g;
        // prefetch B for g+1 (g+1 <= 39 always since g <= 38)
#pragma unroll
        for (int ci = 0; ci < 4; ci++) bb1[ci] = __ldg(B4 + (kc + 1) * 32 + cg + 8 * ci);
        // compute g with bb0
        {
            float4 a0 = *(const float4*)(Ar0 + kc * 4);
            float4 a1 = *(const float4*)(Ar1 + kc * 4);
            ulonglong2 a20 = *reinterpret_cast<ulonglong2*>(&a0);
            ulonglong2 a21 = *reinterpret_cast<ulonglong2*>(&a1);
#pragma unroll
            for (int ci = 0; ci < 4; ci++) {
                ulonglong2 b2 = *reinterpret_cast<ulonglong2*>(&bb0[ci]);
                ac[ci]     = fma2(a20.x, b2.x, ac[ci]);
                ac[ci]     = fma2(a20.y, b2.y, ac[ci]);
                ac[4 + ci] = fma2(a21.x, b2.x, ac[4 + ci]);
                ac[4 + ci] = fma2(a21.y, b2.y, ac[4 + ci]);
            }
        }
        // prefetch B for g+2
        if (g + 2 < 40) {
#pragma unroll
            for (int ci = 0; ci < 4; ci++) bb0[ci] = __ldg(B4 + (kc + 2) * 32 + cg + 8 * ci);
        }
        // compute g+1 with bb1
        {
            float4 a0 = *(const float4*)(Ar0 + (kc + 1) * 4);
            float4 a1 = *(const float4*)(Ar1 + (kc + 1) * 4);
            ulonglong2 a20 = *reinterpret_cast<ulonglong2*>(&a0);
            ulonglong2 a21 = *reinterpret_cast<ulonglong2*>(&a1);
#pragma unroll
            for (int ci = 0; ci < 4; ci++) {
                ulonglong2 b2 = *reinterpret_cast<ulonglong2*>(&bb1[ci]);
                ac[ci]     = fma2(a20.x, b2.x, ac[ci]);
                ac[ci]     = fma2(a20.y, b2.y, ac[ci]);
                ac[4 + ci] = fma2(a21.x, b2.x, ac[4 + ci]);
                ac[4 + ci] = fma2(a21.y, b2.y, ac[4 + ci]);
            }
        }
    }
    __syncthreads();   // all warps done reading As; reuse sm for partials

    // stage partials: S[ks][row][33]
    float* S = sm;
#pragma unroll
    for (int rr = 0; rr < 2; rr++)
#pragma unroll
        for (int ci = 0; ci < 4; ci++)
            S[ks * 1056 + (row0 + rr) * 33 + cg + 8 * ci] = fold2(ac[rr * 4 + ci]);
    __syncthreads();

    // reduce 2 partials + epilogue
    {
        int row = tid >> 3, c4 = (tid & 7) * 4;
        float4 s;
        s.x = conv_b[l * HH + c4 + 0];
        s.y = conv_b[l * HH + c4 + 1];
        s.z = conv_b[l * HH + c4 + 2];
        s.w = conv_b[l * HH + c4 + 3];
#pragma unroll
        for (int p = 0; p < 2; p++) {
            const float* Sp = S + p * 1056 + row * 33 + c4;
            s.x += Sp[0]; s.y += Sp[1]; s.z += Sp[2]; s.w += Sp[3];
        }
        if (do_relu) {
            s.x = fmaxf(s.x, 0.f); s.y = fmaxf(s.y, 0.f);
            s.z = fmaxf(s.z, 0.f); s.w = fmaxf(s.w, 0.f);
        }
        float* __restrict__ xout = g_xbuf[inbuf ^ 1];
        *(float4*)&xout[(n0 + row) * HH + c4] = s;
    }
}

// ================= readout (+ zero g_deg for next replay) ====================
__global__ __launch_bounds__(256) void k_final(const int* __restrict__ metal_idx,
                                               const int* __restrict__ loop_edge,
                                               const int* __restrict__ loop_pair,
                                               const float* __restrict__ f_w,
                                               const float* __restrict__ f_b,
                                               float* __restrict__ out) {
    int gid = blockIdx.x * 256 + threadIdx.x;
    if (gid < NN) g_deg[gid] = 0;

    int gw = blockIdx.x * 8 + (threadIdx.x >> 5);
    int lane = threadIdx.x & 31;
    int b = gw >> 7, p = gw & 127;
    const float* __restrict__ x = g_xbuf[0];   // NLAY even -> final in buf 0

    int mnode = b * NPERB + metal_idx[b];
    float xm = x[mnode * HH + lane];

    int s, t;
    if (p < 64) {
        s = loop_edge[(b * 64 + p) * 2 + 0];
        t = loop_edge[(b * 64 + p) * 2 + 1];
    } else {
        int q = p - 64;
        s = loop_pair[(b * 64 + q) * 2 + 0];
        t = loop_pair[(b * 64 + q) * 2 + 1];
    }
    float xs = x[(b * NPERB + s) * HH + lane];
    float xt = x[(b * NPERB + t) * HH + lane];
    float v  = xm * (xs + xt) - xs * xt;
    float fh = xm * f_w[lane];
#pragma unroll
    for (int off = 16; off; off >>= 1) {
        v  += __shfl_xor_sync(0xFFFFFFFFu, v, off);
        fh += __shfl_xor_sync(0xFFFFFFFFu, fh, off);
    }
    if (lane == 0)
        out[b * 128 + p] = (p < 64) ? (v - (fh + f_b[0])) : -v;
}

// ================= launch ====================================================
extern "C" void kernel_launch(void* const* d_in, const int* in_sizes, int n_in,
                              void* d_out, int out_size) {
    const int*   x_nodes    = (const int*)d_in[0];
    const int*   edge_index = (const int*)d_in[1];
    const int*   edge_attr  = (const int*)d_in[2];
    const int*   metal_idx  = (const int*)d_in[3];
    const int*   loop_edge  = (const int*)d_in[4];
    const int*   loop_pair  = (const int*)d_in[5];
    const float* node_emb   = (const float*)d_in[6];
    const float* edge_emb   = (const float*)d_in[7];
    const float* lin_w      = (const float*)d_in[8];
    const float* lin_b      = (const float*)d_in[9];
    const float* root_w     = (const float*)d_in[10];
    const float* conv_b     = (const float*)d_in[11];
    const float* f_w        = (const float*)d_in[12];
    const float* f_b        = (const float*)d_in[13];
    float* out = (float*)d_out;

    cudaFuncSetAttribute(k_gemm, cudaFuncAttributeMaxDynamicSharedMemorySize, GSMEMB);

    k_setup       <<<736, 256>>>(x_nodes, node_emb, lin_w, lin_b, root_w, edge_index);
    k_scan_scatter<<<64, 256>>>(edge_index, edge_attr);

    for (int l = 0; l < NLAY; l++) {
        int inb = l & 1;
        k_edge<<<NN / 8, 256>>>(edge_emb, inb, l);
        k_gemm<<<NN / 32, 256, GSMEMB>>>(conv_b, inb, l, (l < NLAY - 1) ? 1 : 0);
    }

    k_final<<<512, 256>>>(metal_idx, loop_edge, loop_pair, f_w, f_b, out);
}

// round 14
// speedup vs baseline: 1.2789x; 1.2789x over previous
#include <cuda_runtime.h>

// ---------------- problem constants ----------------
#define NN    16384     // nodes (B*NPER)
#define EE    65536     // edges
#define HH    32        // hidden
#define BBAT  32        // batch
#define NPERB 512
#define NLAY  4
#define KTOT  320       // 256 (c (x) x) + 32 (bias path) + 32 (root path)
#define NPB   32        // nodes per layer-block
#define APITCH 324      // A pitch: rows 16B-aligned; rg-rows on banks 0/4/8/12 -> conflict-free
// dynamic smem float offsets: As (reused as partial staging: 4*32*33=4224 <= 10368), cs
#define OFF_CS 10368    // 32*324
#define SMEMF  10496
#define SMEMB  (SMEMF * 4)   // 41984 B -> 3 blocks/SM

// ---------------- scratch (static device globals; zero at load) ----------------
__device__ __align__(128) float g_xbuf[2][NN * HH];    // ping-pong node features
__device__ __align__(128) float g_B[NLAY * KTOT * HH]; // chunk-major: [l][kc][col][j], j=k%4
__device__ int   g_deg[NN];                            // zeroed by k_final for next replay
__device__ float g_invdeg[NN];
__device__ int   g_rowstart[NN + 1];
__device__ int   g_cursor[NN];
__device__ int   g_payload[EE];                        // (src<<4)|attr, grouped by dst
__device__ int   g_bsum[64];

// ---------------- f32x2 helpers ----------------
__device__ __forceinline__ unsigned long long fma2(unsigned long long a,
                                                   unsigned long long b,
                                                   unsigned long long c) {
    unsigned long long d;
    asm("fma.rn.f32x2 %0, %1, %2, %3;" : "=l"(d) : "l"(a), "l"(b), "l"(c));
    return d;
}
__device__ __forceinline__ float fold2(unsigned long long v) {
    unsigned int lo, hi;
    asm("mov.b64 {%0, %1}, %2;" : "=r"(lo), "=r"(hi) : "l"(v));
    return __uint_as_float(lo) + __uint_as_float(hi);
}

// ================= K1: fused setup (init x, build B chunk-major, count degs) ==
__global__ __launch_bounds__(256) void k_setup(const int* __restrict__ xn,
                                               const float* __restrict__ nemb,
                                               const float* __restrict__ lin_w,
                                               const float* __restrict__ lin_b,
                                               const float* __restrict__ root_w,
                                               const int* __restrict__ edge_index) {
    int b = blockIdx.x, t = threadIdx.x;
    if (b < 512) {
        int i = b * 256 + t;                 // < NN*HH/4
        int node = i >> 3, q = i & 7;
        float4 v = __ldg((const float4*)(nemb + xn[node] * HH + q * 4));
        ((float4*)g_xbuf[0])[i] = v;
    } else if (b < 672) {
        int i = (b - 512) * 256 + t;         // < 40960
        int l = i / 10240;
        int rem = i - l * 10240;
        int kc = rem >> 7;                   // k-chunk 0..79
        int r2 = rem & 127;
        int c = r2 >> 2, j = r2 & 3;
        int k = kc * 4 + j;
        float v;
        if (k < 256)      v = lin_w[l * 8192 + (k >> 5) * 1024 + (k & 31) * 32 + c];
        else if (k < 288) v = lin_b[l * 1024 + (k - 256) * 32 + c];
        else              v = root_w[l * 1024 + (k - 288) * 32 + c];
        g_B[i] = v;
    } else {
        int i = (b - 672) * 256 + t;         // < EE/4
        int4 d4 = __ldg((const int4*)(edge_index + EE) + i);
        atomicAdd(&g_deg[d4.x], 1);
        atomicAdd(&g_deg[d4.y], 1);
        atomicAdd(&g_deg[d4.z], 1);
        atomicAdd(&g_deg[d4.w], 1);
    }
}

// ================= K2/K3: hierarchical scan (R4 exact) ========================
__global__ __launch_bounds__(256) void k_scan1() {
    __shared__ int sw[8];
    int tid = threadIdx.x, w = tid >> 5, lane = tid & 31;
    int n = blockIdx.x * 256 + tid;
    int d = g_deg[n];
    int s = d;
#pragma unroll
    for (int off = 16; off; off >>= 1) s += __shfl_down_sync(0xFFFFFFFFu, s, off);
    if (lane == 0) sw[w] = s;
    __syncthreads();
    if (tid == 0) {
        int tot = 0;
#pragma unroll
        for (int j = 0; j < 8; j++) tot += sw[j];
        g_bsum[blockIdx.x] = tot;
    }
}

__global__ __launch_bounds__(256) void k_scan2() {
    __shared__ int sb[64];
    __shared__ int sw[8];
    int tid = threadIdx.x, w = tid >> 5, lane = tid & 31;
    int n = blockIdx.x * 256 + tid;
    if (tid < 64) sb[tid] = g_bsum[tid];
    int d = g_deg[n];
    __syncthreads();
    int base = 0;
    for (int j = 0; j < blockIdx.x; j++) base += sb[j];
    int incl = d;
#pragma unroll
    for (int off = 1; off < 32; off <<= 1) {
        int v = __shfl_up_sync(0xFFFFFFFFu, incl, off);
        if (lane >= off) incl += v;
    }
    if (lane == 31) sw[w] = incl;
    __syncthreads();
    int woff = 0;
#pragma unroll
    for (int j = 0; j < 8; j++) if (j < w) woff += sw[j];
    int excl = base + woff + incl - d;
    g_rowstart[n] = excl;
    g_cursor[n]   = excl;
    g_invdeg[n]   = 1.0f / (float)(d > 0 ? d : 1);
    if (n == NN - 1) g_rowstart[NN] = excl + d;
}

// ================= K4: scatter edges into CSR (R4 exact) ======================
__global__ __launch_bounds__(256) void k_scatter(const int* __restrict__ edge_index,
                                                 const int* __restrict__ edge_attr) {
    int e = blockIdx.x * 256 + threadIdx.x;
    int d = edge_index[EE + e];
    int pos = atomicAdd(&g_cursor[d], 1);
    g_payload[pos] = (edge_index[e] << 4) | edge_attr[e];
}

// ================= fused layer ================================================
// Phase 1 (edge agg, R4 exact): 8 warps x 4 interleaved nodes, lane = feature.
//   Writes A (32 x 320, pitch 324) into smem; cols 288..319 = own x (root).
// Phase 2 (GEMM, R9 tile): warp = (ks: k-slice of 80) x (rh: row-half of 16).
//   lane: rg=lane>>3 rows {rh*16+rr*4+rg}, cg=lane&7 cols {cg+8ci}. Per 4-k:
//   4 LDS.128 A (conflict-free) + 4 LDG.128 B (chunk-major, 1 line each,
//   L1-hot: 40KB shared by all blocks) + 32 FFMA2, unroll 2.
// Phase 3: stage 4 k-partials (smem reuse), reduce + epilogue.
__global__ __launch_bounds__(256, 3) void k_layer(const float* __restrict__ eemb,
                                                  const float* __restrict__ conv_b,
                                                  int inbuf, int l, int do_relu) {
    extern __shared__ float smem[];
    float* As = smem;
    float* cs = smem + OFF_CS;
    int tid = threadIdx.x;
    if (tid < 128) cs[tid] = fmaxf(eemb[l * 128 + tid], 0.0f);

    const float* __restrict__ xin = g_xbuf[inbuf];
    int w = tid >> 5, lane = tid & 31;
    int nl0 = w * 4;
    int ng0 = blockIdx.x * NPB + nl0;

    int rs = 0;
    if (lane < 5) rs = g_rowstart[ng0 + lane];
    int r0 = __shfl_sync(0xFFFFFFFFu, rs, 0);
    int r1 = __shfl_sync(0xFFFFFFFFu, rs, 1);
    int r2 = __shfl_sync(0xFFFFFFFFu, rs, 2);
    int r3 = __shfl_sync(0xFFFFFFFFu, rs, 3);
    int r4 = __shfl_sync(0xFFFFFFFFu, rs, 4);
    int beg[4] = {r0, r1, r2, r3};
    int cnt[4] = {r1 - r0, r2 - r1, r3 - r2, r4 - r3};
    int maxc = max(max(cnt[0], cnt[1]), max(cnt[2], cnt[3]));

    float acc[4][9];
#pragma unroll
    for (int i = 0; i < 4; i++)
#pragma unroll
        for (int j = 0; j < 9; j++) acc[i][j] = 0.0f;

    __syncthreads();   // cs ready

    for (int t = 0; t < maxc; t++) {
        int   p[4];
        float xv[4];
#pragma unroll
        for (int i = 0; i < 4; i++) p[i] = (t < cnt[i]) ? g_payload[beg[i] + t] : -1;
#pragma unroll
        for (int i = 0; i < 4; i++)
            xv[i] = (p[i] >= 0) ? __ldg(&xin[(p[i] >> 4) * HH + lane]) : 0.0f;
#pragma unroll
        for (int i = 0; i < 4; i++) {
            const float* cc = &cs[(p[i] & 15) * 8];
#pragma unroll
            for (int j = 0; j < 8; j++) acc[i][j] = fmaf(cc[j], xv[i], acc[i][j]);
            acc[i][8] += xv[i];
        }
    }

#pragma unroll
    for (int i = 0; i < 4; i++) {
        float inv = g_invdeg[ng0 + i];
        float* Arow = As + (nl0 + i) * APITCH;
#pragma unroll
        for (int j = 0; j < 9; j++) Arow[j * 32 + lane] = acc[i][j] * inv;
        Arow[288 + lane] = xin[(ng0 + i) * HH + lane];   // root path, unscaled
    }
    __syncthreads();

    // ---------------- GEMM phase ----------------
    int ks = w & 3, rh = w >> 2;
    int rg = lane >> 3, cg = lane & 7;
    const float4* __restrict__ B4 = (const float4*)(g_B + l * 10240);

    unsigned long long ac[16];
#pragma unroll
    for (int i = 0; i < 16; i++) ac[i] = 0ull;

    int kc0 = ks * 20;
#pragma unroll 2
    for (int g = 0; g < 20; g++) {
        int kc = kc0 + g;
        ulonglong2 a2[4], b2[4];
#pragma unroll
        for (int rr = 0; rr < 4; rr++) {
            float4 a = *(const float4*)(As + (rh * 16 + rr * 4 + rg) * APITCH + kc * 4);
            a2[rr] = *reinterpret_cast<ulonglong2*>(&a);
        }
#pragma unroll
        for (int ci = 0; ci < 4; ci++) {
            float4 bx = __ldg(B4 + kc * 32 + cg + 8 * ci);
            b2[ci] = *reinterpret_cast<ulonglong2*>(&bx);
        }
#pragma unroll
        for (int rr = 0; rr < 4; rr++)
#pragma unroll
            for (int ci = 0; ci < 4; ci++) {
                ac[rr * 4 + ci] = fma2(a2[rr].x, b2[ci].x, ac[rr * 4 + ci]);
                ac[rr * 4 + ci] = fma2(a2[rr].y, b2[ci].y, ac[rr * 4 + ci]);
            }
    }
    __syncthreads();   // all warps done reading As; reuse smem for partials

    // stage partials: S[ks][row][33]
    float* S = smem;
#pragma unroll
    for (int rr = 0; rr < 4; rr++)
#pragma unroll
        for (int ci = 0; ci < 4; ci++)
            S[ks * 1056 + (rh * 16 + rr * 4 + rg) * 33 + cg + 8 * ci] = fold2(ac[rr * 4 + ci]);
    __syncthreads();

    // reduce 4 partials + epilogue
    {
        int row = tid >> 3, c4 = (tid & 7) * 4;
        float4 s;
        s.x = conv_b[l * HH + c4 + 0];
        s.y = conv_b[l * HH + c4 + 1];
        s.z = conv_b[l * HH + c4 + 2];
        s.w = conv_b[l * HH + c4 + 3];
#pragma unroll
        for (int p = 0; p < 4; p++) {
            const float* Sp = S + p * 1056 + row * 33 + c4;
            s.x += Sp[0]; s.y += Sp[1]; s.z += Sp[2]; s.w += Sp[3];
        }
        if (do_relu) {
            s.x = fmaxf(s.x, 0.f); s.y = fmaxf(s.y, 0.f);
            s.z = fmaxf(s.z, 0.f); s.w = fmaxf(s.w, 0.f);
        }
        float* __restrict__ xout = g_xbuf[inbuf ^ 1];
        *(float4*)&xout[(blockIdx.x * NPB + row) * HH + c4] = s;
    }
}

// ================= readout (+ zero g_deg for next replay) ====================
__global__ __launch_bounds__(256) void k_final(const int* __restrict__ metal_idx,
                                               const int* __restrict__ loop_edge,
                                               const int* __restrict__ loop_pair,
                                               const float* __restrict__ f_w,
                                               const float* __restrict__ f_b,
                                               float* __restrict__ out) {
    int gid = blockIdx.x * 256 + threadIdx.x;
    if (gid < NN) g_deg[gid] = 0;

    int gw = blockIdx.x * 8 + (threadIdx.x >> 5);
    int lane = threadIdx.x & 31;
    int b = gw >> 7, p = gw & 127;
    const float* __restrict__ x = g_xbuf[0];   // NLAY even -> final in buf 0

    int mnode = b * NPERB + metal_idx[b];
    float xm = x[mnode * HH + lane];

    int s, t;
    if (p < 64) {
        s = loop_edge[(b * 64 + p) * 2 + 0];
        t = loop_edge[(b * 64 + p) * 2 + 1];
    } else {
        int q = p - 64;
        s = loop_pair[(b * 64 + q) * 2 + 0];
        t = loop_pair[(b * 64 + q) * 2 + 1];
    }
    float xs = x[(b * NPERB + s) * HH + lane];
    float xt = x[(b * NPERB + t) * HH + lane];
    float v  = xm * (xs + xt) - xs * xt;
    float fh = xm * f_w[lane];
#pragma unroll
    for (int off = 16; off; off >>= 1) {
        v  += __shfl_xor_sync(0xFFFFFFFFu, v, off);
        fh += __shfl_xor_sync(0xFFFFFFFFu, fh, off);
    }
    if (lane == 0)
        out[b * 128 + p] = (p < 64) ? (v - (fh + f_b[0])) : -v;
}

// ================= launch ====================================================
extern "C" void kernel_launch(void* const* d_in, const int* in_sizes, int n_in,
                              void* d_out, int out_size) {
    const int*   x_nodes    = (const int*)d_in[0];
    const int*   edge_index = (const int*)d_in[1];
    const int*   edge_attr  = (const int*)d_in[2];
    const int*   metal_idx  = (const int*)d_in[3];
    const int*   loop_edge  = (const int*)d_in[4];
    const int*   loop_pair  = (const int*)d_in[5];
    const float* node_emb   = (const float*)d_in[6];
    const float* edge_emb   = (const float*)d_in[7];
    const float* lin_w      = (const float*)d_in[8];
    const float* lin_b      = (const float*)d_in[9];
    const float* root_w     = (const float*)d_in[10];
    const float* conv_b     = (const float*)d_in[11];
    const float* f_w        = (const float*)d_in[12];
    const float* f_b        = (const float*)d_in[13];
    float* out = (float*)d_out;

    cudaFuncSetAttribute(k_layer, cudaFuncAttributeMaxDynamicSharedMemorySize, SMEMB);

    k_setup  <<<736, 256>>>(x_nodes, node_emb, lin_w, lin_b, root_w, edge_index);
    k_scan1  <<<64, 256>>>();
    k_scan2  <<<64, 256>>>();
    k_scatter<<<256, 256>>>(edge_index, edge_attr);

    for (int l = 0; l < NLAY; l++) {
        int inb = l & 1;
        k_layer<<<NN / NPB, 256, SMEMB>>>(edge_emb, conv_b, inb, l, (l < NLAY - 1) ? 1 : 0);
    }

    k_final<<<512, 256>>>(metal_idx, loop_edge, loop_pair, f_w, f_b, out);
}